// round 7
// baseline (speedup 1.0000x reference)
#include <cuda_runtime.h>
#include <math.h>

#define NN   50000
#define EE   400000
#define IN_CH 128
#define HID  256
#define TD   64
#define MSGD 64
#define EDIM 128
#define CH   32

// ---------------- device scratch (no allocs allowed) ----------------
static const size_t OFF_Q1 = 0;
static const size_t OFF_K1 = OFF_Q1 + (size_t)NN*HID;
static const size_t OFF_V1 = OFF_K1 + (size_t)NN*HID;
static const size_t OFF_S1 = OFF_V1 + (size_t)NN*HID;
static const size_t OFF_H  = OFF_S1 + (size_t)NN*HID;
static const size_t OFF_EA = OFF_H  + (size_t)NN*HID;
static const size_t OFF_E1 = OFF_EA + (size_t)EE*EDIM;
static const size_t OFF_E2 = OFF_E1 + (size_t)EE*HID;
static const size_t OFF_Q2 = OFF_E2 + (size_t)EE*CH;
static const size_t OFF_K2 = OFF_Q2 + (size_t)NN*CH;
static const size_t OFF_V2 = OFF_K2 + (size_t)NN*CH;
static const size_t OFF_S2 = OFF_V2 + (size_t)NN*CH;
static const size_t BUF_TOTAL = OFF_S2 + (size_t)NN*CH;   // ~236.8M floats

__device__ __align__(16) float g_buf[BUF_TOTAL];

__device__ int g_cnt[NN];
__device__ int g_cur[NN];
__device__ int g_off[NN + 1];
__device__ int g_src[EE];
__device__ int g_perm[EE];

// ---------------- CSR build ----------------
__global__ void k_zero() {
    int i = blockIdx.x * blockDim.x + threadIdx.x;
    if (i < NN) { g_cnt[i] = 0; g_cur[i] = 0; }
}

// edge_index is int32 (JAX x64 disabled: jnp.int64 request silently yields int32)
__global__ void k_hist(const int* __restrict__ ei) {
    int i = blockIdx.x * blockDim.x + threadIdx.x;
    if (i < EE) {
        int d = ei[EE + i];
        atomicAdd(&g_cnt[d], 1);
    }
}

// single-block exclusive scan over g_cnt -> g_off
__global__ void k_scan() {
    __shared__ int sh[1024];
    __shared__ int s_run;
    int tid = threadIdx.x;
    if (tid == 0) s_run = 0;
    __syncthreads();
    const int nch = (NN + 1023) / 1024;
    for (int c = 0; c < nch; c++) {
        int i = c * 1024 + tid;
        int v = (i < NN) ? g_cnt[i] : 0;
        sh[tid] = v;
        __syncthreads();
        for (int o = 1; o < 1024; o <<= 1) {
            int tmp = (tid >= o) ? sh[tid - o] : 0;
            __syncthreads();
            sh[tid] += tmp;
            __syncthreads();
        }
        int incl = sh[tid];
        if (i < NN) g_off[i] = s_run + incl - v;
        __syncthreads();
        if (tid == 1023) s_run += incl;
        __syncthreads();
    }
    if (tid == 0) g_off[NN] = s_run;
}

__global__ void k_scatter(const int* __restrict__ ei) {
    int i = blockIdx.x * blockDim.x + threadIdx.x;
    if (i < EE) {
        int d = ei[EE + i];
        int s = ei[i];
        int pos = g_off[d] + atomicAdd(&g_cur[d], 1);
        g_src[pos]  = s;
        g_perm[pos] = i;
    }
}

// ---------------- edge attr (sorted order): [cos(rel_t*tw+tb), msg] ----------------
__global__ void k_ea(const float* __restrict__ lu, const float* __restrict__ t,
                     const float* __restrict__ msg, const float* __restrict__ tw,
                     const float* __restrict__ tb) {
    long long idx = (long long)blockIdx.x * blockDim.x + threadIdx.x;
    if (idx >= (long long)EE * EDIM) return;
    int j = (int)(idx >> 7);
    int c = (int)(idx & 127);
    int e = g_perm[j];
    float val;
    if (c < TD) {
        float rel = lu[g_src[j]] - t[e];
        val = cosf(rel * tw[c] + tb[c]);
    } else {
        val = msg[(size_t)e * MSGD + (c - TD)];
    }
    g_buf[OFF_EA + idx] = val;
}

// ---------------- fp32 SGEMM: C[M,Nc] = A[M,K] @ W[K,Nc] (+bias) ----------------
// BM=BN=64, BK=16, 256 threads, 4x4 per thread.
__global__ void sgemm_bias(const float* __restrict__ Aext, size_t aOff,
                           const float* __restrict__ W,
                           const float* __restrict__ bias,
                           size_t cOff, int M, int K, int Nc) {
    const float* A = Aext ? Aext : (g_buf + aOff);
    float* C = g_buf + cOff;

    __shared__ float As[16][64];
    __shared__ float Bs[16][64];
    const int tid = threadIdx.x;
    const int tx  = tid & 15;
    const int ty  = tid >> 4;
    const int rowBase = blockIdx.y * 64;
    const int colBase = blockIdx.x * 64;

    const int ar = tid >> 2;          // 0..63
    const int ak = (tid & 3) * 4;     // 0,4,8,12
    const int wk = tid >> 4;          // 0..15
    const int wc = (tid & 15) * 4;    // 0..60

    float acc[4][4];
#pragma unroll
    for (int i = 0; i < 4; i++)
#pragma unroll
        for (int j = 0; j < 4; j++) acc[i][j] = 0.f;

    for (int k0 = 0; k0 < K; k0 += 16) {
        int gr = rowBase + ar;
        if (gr < M) {
            float4 av = *reinterpret_cast<const float4*>(A + (size_t)gr * K + k0 + ak);
            As[ak + 0][ar] = av.x; As[ak + 1][ar] = av.y;
            As[ak + 2][ar] = av.z; As[ak + 3][ar] = av.w;
        } else {
            As[ak + 0][ar] = 0.f; As[ak + 1][ar] = 0.f;
            As[ak + 2][ar] = 0.f; As[ak + 3][ar] = 0.f;
        }
        int gc = colBase + wc;
        const float* wrow = W + (size_t)(k0 + wk) * Nc;
        if (gc + 3 < Nc) {
            float4 wv = *reinterpret_cast<const float4*>(wrow + gc);
            Bs[wk][wc + 0] = wv.x; Bs[wk][wc + 1] = wv.y;
            Bs[wk][wc + 2] = wv.z; Bs[wk][wc + 3] = wv.w;
        } else {
#pragma unroll
            for (int u = 0; u < 4; u++)
                Bs[wk][wc + u] = (gc + u < Nc) ? wrow[gc + u] : 0.f;
        }
        __syncthreads();
#pragma unroll
        for (int kk = 0; kk < 16; kk++) {
            float a[4], b[4];
#pragma unroll
            for (int i = 0; i < 4; i++) a[i] = As[kk][ty * 4 + i];
#pragma unroll
            for (int j = 0; j < 4; j++) b[j] = Bs[kk][tx * 4 + j];
#pragma unroll
            for (int i = 0; i < 4; i++)
#pragma unroll
                for (int j = 0; j < 4; j++) acc[i][j] += a[i] * b[j];
        }
        __syncthreads();
    }
#pragma unroll
    for (int i = 0; i < 4; i++) {
        int gr = rowBase + ty * 4 + i;
        if (gr >= M) continue;
#pragma unroll
        for (int j = 0; j < 4; j++) {
            int gc = colBase + tx * 4 + j;
            if (gc < Nc) {
                float bv = bias ? bias[gc] : 0.f;
                C[(size_t)gr * Nc + gc] = acc[i][j] + bv;
            }
        }
    }
}

// ---------------- layer 1: fused online segment-softmax + aggregate ----------------
__global__ void k_layer1() {
    int gt   = blockIdx.x * blockDim.x + threadIdx.x;
    int warp = gt >> 5;
    int lane = gt & 31;
    if (warp >= NN) return;
    int d = warp;

    const float* Q1 = g_buf + OFF_Q1 + (size_t)d * HID;
    float q[8], m[8], s[8], acc[8];
#pragma unroll
    for (int i = 0; i < 8; i++) {
        q[i] = Q1[i * 32 + lane];
        m[i] = -INFINITY; s[i] = 0.f; acc[i] = 0.f;
    }
    int beg = g_off[d], end = g_off[d + 1];
    for (int j = beg; j < end; j++) {
        int src = g_src[j];
        const float* K1 = g_buf + OFF_K1 + (size_t)src * HID;
        const float* V1 = g_buf + OFF_V1 + (size_t)src * HID;
        const float* E1 = g_buf + OFF_E1 + (size_t)j   * HID;
        float kv[8], vv[8], ev[8], p[8];
#pragma unroll
        for (int i = 0; i < 8; i++) {
            kv[i] = K1[i * 32 + lane];
            ev[i] = E1[i * 32 + lane];
            vv[i] = V1[i * 32 + lane];
            p[i]  = q[i] * (kv[i] + ev[i]);
        }
#pragma unroll
        for (int o = 16; o >= 1; o >>= 1) {
#pragma unroll
            for (int i = 0; i < 8; i++) p[i] += __shfl_xor_sync(0xffffffffu, p[i], o);
        }
#pragma unroll
        for (int i = 0; i < 8; i++) {
            float a  = p[i] * 0.17677669529663687f;   // 1/sqrt(32)
            float mn = fmaxf(m[i], a);
            float sc = __expf(m[i] - mn);
            float w  = __expf(a - mn);
            s[i]   = s[i] * sc + w;
            acc[i] = acc[i] * sc + w * (vv[i] + ev[i]);
            m[i]   = mn;
        }
    }
    const float* S1 = g_buf + OFF_S1 + (size_t)d * HID;
    float* H = g_buf + OFF_H + (size_t)d * HID;
#pragma unroll
    for (int i = 0; i < 8; i++) {
        float o = acc[i] / (s[i] + 1e-16f) + S1[i * 32 + lane];
        H[i * 32 + lane] = fmaxf(o, 0.f);
    }
}

// ---------------- layer 2: single head, fused ----------------
__global__ void k_layer2(float* __restrict__ out) {
    int gt   = blockIdx.x * blockDim.x + threadIdx.x;
    int warp = gt >> 5;
    int lane = gt & 31;
    if (warp >= NN) return;
    int d = warp;

    float q = g_buf[OFF_Q2 + (size_t)d * CH + lane];
    float m = -INFINITY, s = 0.f, acc = 0.f;
    int beg = g_off[d], end = g_off[d + 1];
    for (int j = beg; j < end; j++) {
        int src = g_src[j];
        float e = g_buf[OFF_E2 + (size_t)j   * CH + lane];
        float k = g_buf[OFF_K2 + (size_t)src * CH + lane] + e;
        float v = g_buf[OFF_V2 + (size_t)src * CH + lane] + e;
        float p = q * k;
#pragma unroll
        for (int o = 16; o >= 1; o >>= 1) p += __shfl_xor_sync(0xffffffffu, p, o);
        float a  = p * 0.17677669529663687f;
        float mn = fmaxf(m, a);
        float sc = __expf(m - mn);
        float w  = __expf(a - mn);
        s   = s * sc + w;
        acc = acc * sc + w * v;
        m   = mn;
    }
    float o = acc / (s + 1e-16f) + g_buf[OFF_S2 + (size_t)d * CH + lane];
    out[(size_t)d * CH + lane] = fmaxf(o, 0.f);
}

// ---------------- host ----------------
extern "C" void kernel_launch(void* const* d_in, const int* in_sizes, int n_in,
                              void* d_out, int out_size) {
    const float* x   = (const float*)d_in[0];
    const float* lu  = (const float*)d_in[1];
    const int*   ei  = (const int*)d_in[2];     // int32! (JAX x64 disabled)
    const float* t   = (const float*)d_in[3];
    const float* msg = (const float*)d_in[4];
    const float* tw  = (const float*)d_in[5];
    const float* tb  = (const float*)d_in[6];
    const float* Wq1 = (const float*)d_in[7];  const float* bq1 = (const float*)d_in[8];
    const float* Wk1 = (const float*)d_in[9];  const float* bk1 = (const float*)d_in[10];
    const float* Wv1 = (const float*)d_in[11]; const float* bv1 = (const float*)d_in[12];
    const float* We1 = (const float*)d_in[13];
    const float* Ws1 = (const float*)d_in[14]; const float* bs1 = (const float*)d_in[15];
    const float* Wq2 = (const float*)d_in[16]; const float* bq2 = (const float*)d_in[17];
    const float* Wk2 = (const float*)d_in[18]; const float* bk2 = (const float*)d_in[19];
    const float* Wv2 = (const float*)d_in[20]; const float* bv2 = (const float*)d_in[21];
    const float* We2 = (const float*)d_in[22];
    const float* Ws2 = (const float*)d_in[23]; const float* bs2 = (const float*)d_in[24];
    float* out = (float*)d_out;

    // CSR build
    k_zero<<<(NN + 255) / 256, 256>>>();
    k_hist<<<(EE + 255) / 256, 256>>>(ei);
    k_scan<<<1, 1024>>>();
    k_scatter<<<(EE + 255) / 256, 256>>>(ei);

    // sorted edge attributes
    {
        long long tot = (long long)EE * EDIM;
        k_ea<<<(unsigned)((tot + 255) / 256), 256>>>(lu, t, msg, tw, tb);
    }

    // layer-1 GEMMs
    dim3 gN1((HID + 63) / 64, (NN + 63) / 64);
    sgemm_bias<<<gN1, 256>>>(x, 0, Wq1, bq1, OFF_Q1, NN, IN_CH, HID);
    sgemm_bias<<<gN1, 256>>>(x, 0, Wk1, bk1, OFF_K1, NN, IN_CH, HID);
    sgemm_bias<<<gN1, 256>>>(x, 0, Wv1, bv1, OFF_V1, NN, IN_CH, HID);
    sgemm_bias<<<gN1, 256>>>(x, 0, Ws1, bs1, OFF_S1, NN, IN_CH, HID);
    dim3 gE1((HID + 63) / 64, (EE + 63) / 64);
    sgemm_bias<<<gE1, 256>>>(nullptr, OFF_EA, We1, nullptr, OFF_E1, EE, EDIM, HID);

    // layer-1 attention + skip + relu
    k_layer1<<<(NN * 32 + 255) / 256, 256>>>();

    // layer-2 GEMMs
    dim3 gN2((CH + 63) / 64, (NN + 63) / 64);
    sgemm_bias<<<gN2, 256>>>(nullptr, OFF_H, Wq2, bq2, OFF_Q2, NN, HID, CH);
    sgemm_bias<<<gN2, 256>>>(nullptr, OFF_H, Wk2, bk2, OFF_K2, NN, HID, CH);
    sgemm_bias<<<gN2, 256>>>(nullptr, OFF_H, Wv2, bv2, OFF_V2, NN, HID, CH);
    sgemm_bias<<<gN2, 256>>>(nullptr, OFF_H, Ws2, bs2, OFF_S2, NN, HID, CH);
    dim3 gE2((CH + 63) / 64, (EE + 63) / 64);
    sgemm_bias<<<gE2, 256>>>(nullptr, OFF_EA, We2, nullptr, OFF_E2, EE, EDIM, CH);

    // layer-2 attention + skip + relu -> output
    k_layer2<<<(NN * 32 + 255) / 256, 256>>>(out);
}

// round 11
// speedup vs baseline: 1.3671x; 1.3671x over previous
#include <cuda_runtime.h>
#include <math.h>

#define NN   50000
#define EE   400000
#define IN_CH 128
#define HID  256
#define TD   64
#define MSGD 64
#define EDIM 128
#define CH   32

// ---------------- device scratch layout (element offsets) ----------------
// L1 : [NN,1024]  merged Q1|K1|V1|S1 (cols 0/256/512/768)
// H  : [NN,256]
// EA : [EE,128]
// E1 : [EE,256]
// L2 : [NN,128]   merged Q2|K2|V2|S2 (cols 0/32/64/96)
// E2 : [EE,32]
// WC1: [128,1024] concat layer1 node weights ; BC1: [1024]
// WC2: [256,128]  concat layer2 node weights ; BC2: [128]
static const size_t OFF_L1  = 0;
static const size_t OFF_H   = OFF_L1  + (size_t)NN*1024;
static const size_t OFF_EA  = OFF_H   + (size_t)NN*256;
static const size_t OFF_E1  = OFF_EA  + (size_t)EE*128;
static const size_t OFF_L2  = OFF_E1  + (size_t)EE*256;
static const size_t OFF_E2  = OFF_L2  + (size_t)NN*128;
static const size_t OFF_WC1 = OFF_E2  + (size_t)EE*32;
static const size_t OFF_BC1 = OFF_WC1 + (size_t)128*1024;
static const size_t OFF_WC2 = OFF_BC1 + 1024;
static const size_t OFF_BC2 = OFF_WC2 + (size_t)256*128;
static const size_t BUF_TOTAL = OFF_BC2 + 128;

__device__ __align__(16) float g_buf[BUF_TOTAL];

__device__ int g_cnt[NN];
__device__ int g_cur[NN];
__device__ int g_off[NN + 1];
__device__ int g_src[EE];
__device__ int g_perm[EE];

// ---------------- CSR build ----------------
__global__ void k_zero() {
    int i = blockIdx.x * blockDim.x + threadIdx.x;
    if (i < NN) { g_cnt[i] = 0; g_cur[i] = 0; }
}

// edge_index is int32 (JAX x64 disabled)
__global__ void k_hist(const int* __restrict__ ei) {
    int i = blockIdx.x * blockDim.x + threadIdx.x;
    if (i < EE) atomicAdd(&g_cnt[ei[EE + i]], 1);
}

__global__ void k_scan() {
    __shared__ int sh[1024];
    __shared__ int s_run;
    int tid = threadIdx.x;
    if (tid == 0) s_run = 0;
    __syncthreads();
    const int nch = (NN + 1023) / 1024;
    for (int c = 0; c < nch; c++) {
        int i = c * 1024 + tid;
        int v = (i < NN) ? g_cnt[i] : 0;
        sh[tid] = v;
        __syncthreads();
        for (int o = 1; o < 1024; o <<= 1) {
            int tmp = (tid >= o) ? sh[tid - o] : 0;
            __syncthreads();
            sh[tid] += tmp;
            __syncthreads();
        }
        int incl = sh[tid];
        if (i < NN) g_off[i] = s_run + incl - v;
        __syncthreads();
        if (tid == 1023) s_run += incl;
        __syncthreads();
    }
    if (tid == 0) g_off[NN] = s_run;
}

__global__ void k_scatter(const int* __restrict__ ei) {
    int i = blockIdx.x * blockDim.x + threadIdx.x;
    if (i < EE) {
        int d = ei[EE + i];
        int s = ei[i];
        int pos = g_off[d] + atomicAdd(&g_cur[d], 1);
        g_src[pos]  = s;
        g_perm[pos] = i;
    }
}

// ---------------- weight concat ----------------
__global__ void k_cat1(const float* __restrict__ Wq, const float* __restrict__ Wk,
                       const float* __restrict__ Wv, const float* __restrict__ Ws,
                       const float* __restrict__ bq, const float* __restrict__ bk,
                       const float* __restrict__ bv, const float* __restrict__ bs) {
    int idx = blockIdx.x * blockDim.x + threadIdx.x;
    if (idx < 128 * 1024) {
        int k = idx >> 10, r = idx & 1023;
        int g = r >> 8, c = r & 255;
        const float* W = (g == 0) ? Wq : (g == 1) ? Wk : (g == 2) ? Wv : Ws;
        g_buf[OFF_WC1 + idx] = W[k * 256 + c];
    } else if (idx < 128 * 1024 + 1024) {
        int bi = idx - 128 * 1024;
        int g = bi >> 8, c = bi & 255;
        const float* b = (g == 0) ? bq : (g == 1) ? bk : (g == 2) ? bv : bs;
        g_buf[OFF_BC1 + bi] = b[c];
    }
}

__global__ void k_cat2(const float* __restrict__ Wq, const float* __restrict__ Wk,
                       const float* __restrict__ Wv, const float* __restrict__ Ws,
                       const float* __restrict__ bq, const float* __restrict__ bk,
                       const float* __restrict__ bv, const float* __restrict__ bs) {
    int idx = blockIdx.x * blockDim.x + threadIdx.x;
    if (idx < 256 * 128) {
        int k = idx >> 7, r = idx & 127;
        int g = r >> 5, c = r & 31;
        const float* W = (g == 0) ? Wq : (g == 1) ? Wk : (g == 2) ? Wv : Ws;
        g_buf[OFF_WC2 + idx] = W[k * 32 + c];
    } else if (idx < 256 * 128 + 128) {
        int bi = idx - 256 * 128;
        int g = bi >> 5, c = bi & 31;
        const float* b = (g == 0) ? bq : (g == 1) ? bk : (g == 2) ? bv : bs;
        g_buf[OFF_BC2 + bi] = b[c];
    }
}

// ---------------- edge attr (sorted order): [cos(rel_t*tw+tb), msg] ----------------
__global__ void k_ea(const float* __restrict__ lu, const float* __restrict__ t,
                     const float* __restrict__ msg, const float* __restrict__ tw,
                     const float* __restrict__ tb) {
    long long idx = (long long)blockIdx.x * blockDim.x + threadIdx.x;
    if (idx >= (long long)EE * EDIM) return;
    int j = (int)(idx >> 7);
    int c = (int)(idx & 127);
    int e = g_perm[j];
    float val;
    if (c < TD) {
        float rel = lu[g_src[j]] - t[e];
        val = cosf(rel * tw[c] + tb[c]);
    } else {
        val = msg[(size_t)e * MSGD + (c - TD)];
    }
    g_buf[OFF_EA + idx] = val;
}

// ---------------- SGEMM 128x128, BK=16, 256 threads, 8x8/thread ----------------
// C[M,Nc] = A[M,K] @ W[K,Nc] (+bias). A/W/bias either external or g_buf+offset.
// Thread columns: tx*4+{0..3} and 64+tx*4+{0..3} (contiguous LDS per half-warp).
__global__ __launch_bounds__(256) void sgemm_128(
    const float* __restrict__ Aext, size_t aOff,
    const float* __restrict__ Wext, size_t wOff,
    int hasBias, size_t bOff,
    size_t cOff, int M, int K, int Nc) {
    const float* A = Aext ? Aext : (g_buf + aOff);
    const float* W = Wext ? Wext : (g_buf + wOff);
    float* C = g_buf + cOff;

    __shared__ float As[16][128];
    __shared__ float Bs[16][128];

    const int tid = threadIdx.x;
    const int tx = tid & 15;
    const int ty = tid >> 4;
    const int rowBase = blockIdx.y * 128;
    const int colBase = blockIdx.x * 128;

    float acc[8][8];
#pragma unroll
    for (int i = 0; i < 8; i++)
#pragma unroll
        for (int j = 0; j < 8; j++) acc[i][j] = 0.f;

    for (int k0 = 0; k0 < K; k0 += 16) {
        // A tile: 128 rows x 16 k = 512 float4; transpose into As[k][row]
#pragma unroll
        for (int i = 0; i < 2; i++) {
            int idx = tid + i * 256;         // 0..511
            int r  = idx >> 2;
            int kc = (idx & 3) << 2;
            int gr = rowBase + r;
            float4 v = make_float4(0.f, 0.f, 0.f, 0.f);
            if (gr < M) v = *reinterpret_cast<const float4*>(A + (size_t)gr * K + k0 + kc);
            As[kc + 0][r] = v.x; As[kc + 1][r] = v.y;
            As[kc + 2][r] = v.z; As[kc + 3][r] = v.w;
        }
        // B tile: 16 k x 128 cols
#pragma unroll
        for (int i = 0; i < 2; i++) {
            int idx = tid + i * 256;
            int kk = idx >> 5;
            int cc = (idx & 31) << 2;
            float4 v = *reinterpret_cast<const float4*>(W + (size_t)(k0 + kk) * Nc + colBase + cc);
            *reinterpret_cast<float4*>(&Bs[kk][cc]) = v;
        }
        __syncthreads();
#pragma unroll
        for (int kk = 0; kk < 16; kk++) {
            float a[8], b[8];
            *reinterpret_cast<float4*>(&a[0]) = *reinterpret_cast<float4*>(&As[kk][ty * 8]);
            *reinterpret_cast<float4*>(&a[4]) = *reinterpret_cast<float4*>(&As[kk][ty * 8 + 4]);
            *reinterpret_cast<float4*>(&b[0]) = *reinterpret_cast<float4*>(&Bs[kk][tx * 4]);
            *reinterpret_cast<float4*>(&b[4]) = *reinterpret_cast<float4*>(&Bs[kk][64 + tx * 4]);
#pragma unroll
            for (int i = 0; i < 8; i++)
#pragma unroll
                for (int j = 0; j < 8; j++) acc[i][j] += a[i] * b[j];
        }
        __syncthreads();
    }

    // store: cols colBase + tx*4 + {0..3} and colBase + 64 + tx*4 + {0..3}
    float4 bias0 = make_float4(0.f, 0.f, 0.f, 0.f), bias1 = bias0;
    if (hasBias) {
        const float* bias = g_buf + bOff;
        bias0 = *reinterpret_cast<const float4*>(bias + colBase + tx * 4);
        bias1 = *reinterpret_cast<const float4*>(bias + colBase + 64 + tx * 4);
    }
#pragma unroll
    for (int i = 0; i < 8; i++) {
        int gr = rowBase + ty * 8 + i;
        if (gr >= M) continue;
        float4 v0 = make_float4(acc[i][0] + bias0.x, acc[i][1] + bias0.y,
                                acc[i][2] + bias0.z, acc[i][3] + bias0.w);
        float4 v1 = make_float4(acc[i][4] + bias1.x, acc[i][5] + bias1.y,
                                acc[i][6] + bias1.z, acc[i][7] + bias1.w);
        *reinterpret_cast<float4*>(C + (size_t)gr * Nc + colBase + tx * 4) = v0;
        *reinterpret_cast<float4*>(C + (size_t)gr * Nc + colBase + 64 + tx * 4) = v1;
    }
}

// ---------------- SGEMM 128x32 (for E2), 64 threads, 8x8/thread, no bias ----------------
__global__ __launch_bounds__(64) void sgemm_32(
    size_t aOff, const float* __restrict__ W,
    size_t cOff, int M, int K, int Nc) {
    const float* A = g_buf + aOff;
    float* C = g_buf + cOff;

    __shared__ float As[16][128];
    __shared__ float Bs[16][32];

    const int tid = threadIdx.x;
    const int tx = tid & 3;       // 4 col groups
    const int ty = tid >> 2;      // 16 row groups
    const int rowBase = blockIdx.y * 128;

    float acc[8][8];
#pragma unroll
    for (int i = 0; i < 8; i++)
#pragma unroll
        for (int j = 0; j < 8; j++) acc[i][j] = 0.f;

    for (int k0 = 0; k0 < K; k0 += 16) {
#pragma unroll
        for (int i = 0; i < 8; i++) {
            int idx = tid + i * 64;          // 0..511
            int r  = idx >> 2;
            int kc = (idx & 3) << 2;
            int gr = rowBase + r;
            float4 v = make_float4(0.f, 0.f, 0.f, 0.f);
            if (gr < M) v = *reinterpret_cast<const float4*>(A + (size_t)gr * K + k0 + kc);
            As[kc + 0][r] = v.x; As[kc + 1][r] = v.y;
            As[kc + 2][r] = v.z; As[kc + 3][r] = v.w;
        }
#pragma unroll
        for (int i = 0; i < 2; i++) {
            int idx = tid + i * 64;          // 0..127
            int kk = idx >> 3;
            int cc = (idx & 7) << 2;
            float4 v = *reinterpret_cast<const float4*>(W + (size_t)(k0 + kk) * Nc + cc);
            *reinterpret_cast<float4*>(&Bs[kk][cc]) = v;
        }
        __syncthreads();
#pragma unroll
        for (int kk = 0; kk < 16; kk++) {
            float a[8], b[8];
            *reinterpret_cast<float4*>(&a[0]) = *reinterpret_cast<float4*>(&As[kk][ty * 8]);
            *reinterpret_cast<float4*>(&a[4]) = *reinterpret_cast<float4*>(&As[kk][ty * 8 + 4]);
            *reinterpret_cast<float4*>(&b[0]) = *reinterpret_cast<float4*>(&Bs[kk][tx * 4]);
            *reinterpret_cast<float4*>(&b[4]) = *reinterpret_cast<float4*>(&Bs[kk][16 + tx * 4]);
#pragma unroll
            for (int i = 0; i < 8; i++)
#pragma unroll
                for (int j = 0; j < 8; j++) acc[i][j] += a[i] * b[j];
        }
        __syncthreads();
    }
#pragma unroll
    for (int i = 0; i < 8; i++) {
        int gr = rowBase + ty * 8 + i;
        if (gr >= M) continue;
        float4 v0 = make_float4(acc[i][0], acc[i][1], acc[i][2], acc[i][3]);
        float4 v1 = make_float4(acc[i][4], acc[i][5], acc[i][6], acc[i][7]);
        *reinterpret_cast<float4*>(C + (size_t)gr * Nc + tx * 4) = v0;
        *reinterpret_cast<float4*>(C + (size_t)gr * Nc + 16 + tx * 4) = v1;
    }
}

// ---------------- layer 1: fused online segment-softmax + aggregate ----------------
// one warp per dst node; lane l owns columns {l, l+32, ..., l+224}; head i = column/32
__global__ void k_layer1() {
    int gt   = blockIdx.x * blockDim.x + threadIdx.x;
    int warp = gt >> 5;
    int lane = gt & 31;
    if (warp >= NN) return;
    int d = warp;

    const float* Q1 = g_buf + OFF_L1 + (size_t)d * 1024;          // cols 0..255
    float q[8], m[8], s[8], acc[8];
#pragma unroll
    for (int i = 0; i < 8; i++) {
        q[i] = Q1[i * 32 + lane];
        m[i] = -INFINITY; s[i] = 0.f; acc[i] = 0.f;
    }
    int beg = g_off[d], end = g_off[d + 1];
    for (int j = beg; j < end; j++) {
        int src = g_src[j];
        const float* K1 = g_buf + OFF_L1 + (size_t)src * 1024 + 256;
        const float* V1 = g_buf + OFF_L1 + (size_t)src * 1024 + 512;
        const float* E1 = g_buf + OFF_E1 + (size_t)j * 256;
        float kv[8], vv[8], ev[8], p[8];
#pragma unroll
        for (int i = 0; i < 8; i++) {
            kv[i] = K1[i * 32 + lane];
            ev[i] = E1[i * 32 + lane];
            vv[i] = V1[i * 32 + lane];
            p[i]  = q[i] * (kv[i] + ev[i]);
        }
#pragma unroll
        for (int o = 16; o >= 1; o >>= 1) {
#pragma unroll
            for (int i = 0; i < 8; i++) p[i] += __shfl_xor_sync(0xffffffffu, p[i], o);
        }
#pragma unroll
        for (int i = 0; i < 8; i++) {
            float a  = p[i] * 0.17677669529663687f;   // 1/sqrt(32)
            float mn = fmaxf(m[i], a);
            float sc = __expf(m[i] - mn);
            float w  = __expf(a - mn);
            s[i]   = s[i] * sc + w;
            acc[i] = acc[i] * sc + w * (vv[i] + ev[i]);
            m[i]   = mn;
        }
    }
    const float* S1 = g_buf + OFF_L1 + (size_t)d * 1024 + 768;
    float* H = g_buf + OFF_H + (size_t)d * 256;
#pragma unroll
    for (int i = 0; i < 8; i++) {
        float o = acc[i] / (s[i] + 1e-16f) + S1[i * 32 + lane];
        H[i * 32 + lane] = fmaxf(o, 0.f);
    }
}

// ---------------- layer 2: single head, fused ----------------
__global__ void k_layer2(float* __restrict__ out) {
    int gt   = blockIdx.x * blockDim.x + threadIdx.x;
    int warp = gt >> 5;
    int lane = gt & 31;
    if (warp >= NN) return;
    int d = warp;

    float q = g_buf[OFF_L2 + (size_t)d * 128 + lane];
    float m = -INFINITY, s = 0.f, acc = 0.f;
    int beg = g_off[d], end = g_off[d + 1];
    for (int j = beg; j < end; j++) {
        int src = g_src[j];
        float e = g_buf[OFF_E2 + (size_t)j * 32 + lane];
        float k = g_buf[OFF_L2 + (size_t)src * 128 + 32 + lane] + e;
        float v = g_buf[OFF_L2 + (size_t)src * 128 + 64 + lane] + e;
        float p = q * k;
#pragma unroll
        for (int o = 16; o >= 1; o >>= 1) p += __shfl_xor_sync(0xffffffffu, p, o);
        float a  = p * 0.17677669529663687f;
        float mn = fmaxf(m, a);
        float sc = __expf(m - mn);
        float w  = __expf(a - mn);
        s   = s * sc + w;
        acc = acc * sc + w * v;
        m   = mn;
    }
    float o = acc / (s + 1e-16f) + g_buf[OFF_L2 + (size_t)d * 128 + 96 + lane];
    out[(size_t)d * CH + lane] = fmaxf(o, 0.f);
}

// ---------------- host ----------------
extern "C" void kernel_launch(void* const* d_in, const int* in_sizes, int n_in,
                              void* d_out, int out_size) {
    const float* x   = (const float*)d_in[0];
    const float* lu  = (const float*)d_in[1];
    const int*   ei  = (const int*)d_in[2];     // int32 (JAX x64 disabled)
    const float* t   = (const float*)d_in[3];
    const float* msg = (const float*)d_in[4];
    const float* tw  = (const float*)d_in[5];
    const float* tb  = (const float*)d_in[6];
    const float* Wq1 = (const float*)d_in[7];  const float* bq1 = (const float*)d_in[8];
    const float* Wk1 = (const float*)d_in[9];  const float* bk1 = (const float*)d_in[10];
    const float* Wv1 = (const float*)d_in[11]; const float* bv1 = (const float*)d_in[12];
    const float* We1 = (const float*)d_in[13];
    const float* Ws1 = (const float*)d_in[14]; const float* bs1 = (const float*)d_in[15];
    const float* Wq2 = (const float*)d_in[16]; const float* bq2 = (const float*)d_in[17];
    const float* Wk2 = (const float*)d_in[18]; const float* bk2 = (const float*)d_in[19];
    const float* Wv2 = (const float*)d_in[20]; const float* bv2 = (const float*)d_in[21];
    const float* We2 = (const float*)d_in[22];
    const float* Ws2 = (const float*)d_in[23]; const float* bs2 = (const float*)d_in[24];
    float* out = (float*)d_out;

    // CSR build
    k_zero<<<(NN + 255) / 256, 256>>>();
    k_hist<<<(EE + 255) / 256, 256>>>(ei);
    k_scan<<<1, 1024>>>();
    k_scatter<<<(EE + 255) / 256, 256>>>(ei);

    // weight concat (independent of CSR)
    k_cat1<<<(128 * 1024 + 1024 + 255) / 256, 256>>>(Wq1, Wk1, Wv1, Ws1, bq1, bk1, bv1, bs1);
    k_cat2<<<(256 * 128 + 128 + 255) / 256, 256>>>(Wq2, Wk2, Wv2, Ws2, bq2, bk2, bv2, bs2);

    // sorted edge attributes
    {
        long long tot = (long long)EE * EDIM;
        k_ea<<<(unsigned)((tot + 255) / 256), 256>>>(lu, t, msg, tw, tb);
    }

    // layer-1 GEMMs: merged node GEMM [NN,128]@[128,1024], edge GEMM [EE,128]@[128,256]
    {
        dim3 g1(1024 / 128, (NN + 127) / 128);
        sgemm_128<<<g1, 256>>>(x, 0, nullptr, OFF_WC1, 1, OFF_BC1, OFF_L1, NN, IN_CH, 1024);
        dim3 gE1(256 / 128, (EE + 127) / 128);
        sgemm_128<<<gE1, 256>>>(nullptr, OFF_EA, We1, 0, 0, 0, OFF_E1, EE, EDIM, HID);
    }

    // layer-1 attention + skip + relu
    k_layer1<<<(NN * 32 + 255) / 256, 256>>>();

    // layer-2 GEMMs: merged node GEMM [NN,256]@[256,128], edge GEMM [EE,128]@[128,32]
    {
        dim3 g2(128 / 128, (NN + 127) / 128);
        sgemm_128<<<g2, 256>>>(nullptr, OFF_H, nullptr, OFF_WC2, 1, OFF_BC2, OFF_L2, NN, HID, 128);
        dim3 gE2(1, (EE + 127) / 128);
        sgemm_32<<<gE2, 64>>>(OFF_EA, We2, OFF_E2, EE, EDIM, CH);
    }

    // layer-2 attention + skip + relu -> output
    k_layer2<<<(NN * 32 + 255) / 256, 256>>>(out);
}

// round 13
// speedup vs baseline: 1.5885x; 1.1619x over previous
#include <cuda_runtime.h>
#include <math.h>

#define NN   50000
#define EE   400000
#define IN_CH 128
#define HID  256
#define TD   64
#define MSGD 64
#define EDIM 128
#define CH   32

// ---------------- device scratch layout (element offsets) ----------------
static const size_t OFF_L1    = 0;                              // [NN,1024] Q1|K1|V1|S1
static const size_t OFF_P1    = OFF_L1    + (size_t)NN*1024;    // [NN,8,128] q-proj
static const size_t OFF_EA    = OFF_P1    + (size_t)NN*1024;    // [EE,128]
static const size_t OFF_ACC1  = OFF_EA    + (size_t)EE*128;     // [NN,256]
static const size_t OFF_AGG1  = OFF_ACC1  + (size_t)NN*256;     // [NN,8,128]
static const size_t OFF_S1V   = OFF_AGG1  + (size_t)NN*1024;    // [NN,8]
static const size_t OFF_AGGP1 = OFF_S1V   + (size_t)NN*8;       // [NN,256]
static const size_t OFF_H     = OFF_AGGP1 + (size_t)NN*256;     // [NN,256]
static const size_t OFF_L2    = OFF_H     + (size_t)NN*256;     // [NN,128] Q2|K2|V2|S2
static const size_t OFF_P2    = OFF_L2    + (size_t)NN*128;     // [NN,128]
static const size_t OFF_ACC2  = OFF_P2    + (size_t)NN*128;     // [NN,32]
static const size_t OFF_AGG2  = OFF_ACC2  + (size_t)NN*32;      // [NN,128]
static const size_t OFF_S2V   = OFF_AGG2  + (size_t)NN*128;     // [NN]
static const size_t OFF_AGGP2 = OFF_S2V   + (size_t)NN;         // [NN,32]
static const size_t OFF_WC1   = OFF_AGGP2 + (size_t)NN*32;      // [128,1024]
static const size_t OFF_BC1   = OFF_WC1   + (size_t)128*1024;   // [1024]
static const size_t OFF_WC2   = OFF_BC1   + 1024;               // [256,128]
static const size_t OFF_BC2   = OFF_WC2   + (size_t)256*128;    // [128]
static const size_t OFF_WT1   = OFF_BC2   + 128;                // [256,128]  We1^T
static const size_t OFF_WT2   = OFF_WT1   + (size_t)256*128;    // [32,128]   We2^T
static const size_t BUF_TOTAL = OFF_WT2   + (size_t)32*128;

__device__ __align__(16) float g_buf[BUF_TOTAL];

__device__ int g_cnt[NN];
__device__ int g_cur[NN];
__device__ int g_off[NN + 1];
__device__ int g_src[EE];
__device__ int g_perm[EE];

// ---------------- CSR build ----------------
__global__ void k_zero() {
    int i = blockIdx.x * blockDim.x + threadIdx.x;
    if (i < NN) { g_cnt[i] = 0; g_cur[i] = 0; }
}

__global__ void k_hist(const int* __restrict__ ei) {
    int i = blockIdx.x * blockDim.x + threadIdx.x;
    if (i < EE) atomicAdd(&g_cnt[ei[EE + i]], 1);
}

__global__ void k_scan() {
    __shared__ int sh[1024];
    __shared__ int s_run;
    int tid = threadIdx.x;
    if (tid == 0) s_run = 0;
    __syncthreads();
    const int nch = (NN + 1023) / 1024;
    for (int c = 0; c < nch; c++) {
        int i = c * 1024 + tid;
        int v = (i < NN) ? g_cnt[i] : 0;
        sh[tid] = v;
        __syncthreads();
        for (int o = 1; o < 1024; o <<= 1) {
            int tmp = (tid >= o) ? sh[tid - o] : 0;
            __syncthreads();
            sh[tid] += tmp;
            __syncthreads();
        }
        int incl = sh[tid];
        if (i < NN) g_off[i] = s_run + incl - v;
        __syncthreads();
        if (tid == 1023) s_run += incl;
        __syncthreads();
    }
    if (tid == 0) g_off[NN] = s_run;
}

__global__ void k_scatter(const int* __restrict__ ei) {
    int i = blockIdx.x * blockDim.x + threadIdx.x;
    if (i < EE) {
        int d = ei[EE + i];
        int s = ei[i];
        int pos = g_off[d] + atomicAdd(&g_cur[d], 1);
        g_src[pos]  = s;
        g_perm[pos] = i;
    }
}

// ---------------- weight prep ----------------
__global__ void k_cat1(const float* __restrict__ Wq, const float* __restrict__ Wk,
                       const float* __restrict__ Wv, const float* __restrict__ Ws,
                       const float* __restrict__ bq, const float* __restrict__ bk,
                       const float* __restrict__ bv, const float* __restrict__ bs) {
    int idx = blockIdx.x * blockDim.x + threadIdx.x;
    if (idx < 128 * 1024) {
        int k = idx >> 10, r = idx & 1023;
        int g = r >> 8, c = r & 255;
        const float* W = (g == 0) ? Wq : (g == 1) ? Wk : (g == 2) ? Wv : Ws;
        g_buf[OFF_WC1 + idx] = W[k * 256 + c];
    } else if (idx < 128 * 1024 + 1024) {
        int bi = idx - 128 * 1024;
        int g = bi >> 8, c = bi & 255;
        const float* b = (g == 0) ? bq : (g == 1) ? bk : (g == 2) ? bv : bs;
        g_buf[OFF_BC1 + bi] = b[c];
    }
}

__global__ void k_cat2(const float* __restrict__ Wq, const float* __restrict__ Wk,
                       const float* __restrict__ Wv, const float* __restrict__ Ws,
                       const float* __restrict__ bq, const float* __restrict__ bk,
                       const float* __restrict__ bv, const float* __restrict__ bs) {
    int idx = blockIdx.x * blockDim.x + threadIdx.x;
    if (idx < 256 * 128) {
        int k = idx >> 7, r = idx & 127;
        int g = r >> 5, c = r & 31;
        const float* W = (g == 0) ? Wq : (g == 1) ? Wk : (g == 2) ? Wv : Ws;
        g_buf[OFF_WC2 + idx] = W[k * 32 + c];
    } else if (idx < 256 * 128 + 128) {
        int bi = idx - 256 * 128;
        int g = bi >> 5, c = bi & 31;
        const float* b = (g == 0) ? bq : (g == 1) ? bk : (g == 2) ? bv : bs;
        g_buf[OFF_BC2 + bi] = b[c];
    }
}

// transposes: WT1[c,f] = We1[f,c]; WT2[c,f] = We2[f,c]
__global__ void k_wt(const float* __restrict__ We1, const float* __restrict__ We2) {
    int idx = blockIdx.x * blockDim.x + threadIdx.x;
    if (idx < 128 * 256) {
        int f = idx >> 8, c = idx & 255;
        g_buf[OFF_WT1 + (size_t)c * 128 + f] = We1[idx];
    } else if (idx < 128 * 256 + 128 * 32) {
        int j = idx - 128 * 256;
        int f = j >> 5, c = j & 31;
        g_buf[OFF_WT2 + (size_t)c * 128 + f] = We2[j];
    }
}

// ---------------- edge attr (sorted order): [cos(rel_t*tw+tb), msg] ----------------
__global__ void k_ea(const float* __restrict__ lu, const float* __restrict__ t,
                     const float* __restrict__ msg, const float* __restrict__ tw,
                     const float* __restrict__ tb) {
    long long idx = (long long)blockIdx.x * blockDim.x + threadIdx.x;
    if (idx >= (long long)EE * EDIM) return;
    int j = (int)(idx >> 7);
    int c = (int)(idx & 127);
    int e = g_perm[j];
    float val;
    if (c < TD) {
        float rel = lu[g_src[j]] - t[e];
        val = cosf(rel * tw[c] + tb[c]);
    } else {
        val = msg[(size_t)e * MSGD + (c - TD)];
    }
    g_buf[OFF_EA + idx] = val;
}

// ---------------- SGEMM 128x128, BK=16, 256 threads, 8x8/thread ----------------
// C = A@W (+bias); A/W external or in g_buf; lda/ldb/ldc strides; blockIdx.z = head
// with per-head offsets ahs/whs/chs.
__global__ __launch_bounds__(256) void sgemm_128(
    const float* __restrict__ Aext, size_t aOff, int lda, size_t ahs,
    const float* __restrict__ Wext, size_t wOff, int ldb, size_t whs,
    int hasBias, size_t bOff,
    size_t cOff, int ldc, size_t chs, int M, int K, int Nc) {
    const float* A = (Aext ? Aext : g_buf) + aOff + (size_t)blockIdx.z * ahs;
    const float* W = (Wext ? Wext : g_buf) + wOff + (size_t)blockIdx.z * whs;
    float* C = g_buf + cOff + (size_t)blockIdx.z * chs;

    __shared__ float As[16][128];
    __shared__ float Bs[16][128];

    const int tid = threadIdx.x;
    const int tx = tid & 15;
    const int ty = tid >> 4;
    const int rowBase = blockIdx.y * 128;
    const int colBase = blockIdx.x * 128;

    float acc[8][8];
#pragma unroll
    for (int i = 0; i < 8; i++)
#pragma unroll
        for (int j = 0; j < 8; j++) acc[i][j] = 0.f;

    for (int k0 = 0; k0 < K; k0 += 16) {
#pragma unroll
        for (int i = 0; i < 2; i++) {
            int idx = tid + i * 256;
            int r  = idx >> 2;
            int kc = (idx & 3) << 2;
            int gr = rowBase + r;
            float4 v = make_float4(0.f, 0.f, 0.f, 0.f);
            if (gr < M) v = *reinterpret_cast<const float4*>(A + (size_t)gr * lda + k0 + kc);
            As[kc + 0][r] = v.x; As[kc + 1][r] = v.y;
            As[kc + 2][r] = v.z; As[kc + 3][r] = v.w;
        }
#pragma unroll
        for (int i = 0; i < 2; i++) {
            int idx = tid + i * 256;
            int kk = idx >> 5;
            int cc = (idx & 31) << 2;
            float4 v = *reinterpret_cast<const float4*>(W + (size_t)(k0 + kk) * ldb + colBase + cc);
            *reinterpret_cast<float4*>(&Bs[kk][cc]) = v;
        }
        __syncthreads();
#pragma unroll
        for (int kk = 0; kk < 16; kk++) {
            float a[8], b[8];
            *reinterpret_cast<float4*>(&a[0]) = *reinterpret_cast<float4*>(&As[kk][ty * 8]);
            *reinterpret_cast<float4*>(&a[4]) = *reinterpret_cast<float4*>(&As[kk][ty * 8 + 4]);
            *reinterpret_cast<float4*>(&b[0]) = *reinterpret_cast<float4*>(&Bs[kk][tx * 4]);
            *reinterpret_cast<float4*>(&b[4]) = *reinterpret_cast<float4*>(&Bs[kk][64 + tx * 4]);
#pragma unroll
            for (int i = 0; i < 8; i++)
#pragma unroll
                for (int j = 0; j < 8; j++) acc[i][j] += a[i] * b[j];
        }
        __syncthreads();
    }

    float4 bias0 = make_float4(0.f, 0.f, 0.f, 0.f), bias1 = bias0;
    if (hasBias) {
        const float* bias = g_buf + bOff;
        bias0 = *reinterpret_cast<const float4*>(bias + colBase + tx * 4);
        bias1 = *reinterpret_cast<const float4*>(bias + colBase + 64 + tx * 4);
    }
#pragma unroll
    for (int i = 0; i < 8; i++) {
        int gr = rowBase + ty * 8 + i;
        if (gr >= M) continue;
        float4 v0 = make_float4(acc[i][0] + bias0.x, acc[i][1] + bias0.y,
                                acc[i][2] + bias0.z, acc[i][3] + bias0.w);
        float4 v1 = make_float4(acc[i][4] + bias1.x, acc[i][5] + bias1.y,
                                acc[i][6] + bias1.z, acc[i][7] + bias1.w);
        *reinterpret_cast<float4*>(C + (size_t)gr * ldc + colBase + tx * 4) = v0;
        *reinterpret_cast<float4*>(C + (size_t)gr * ldc + colBase + 64 + tx * 4) = v1;
    }
}

// ---------------- SGEMM 128x32, 64 threads, 8x8/thread, no bias ----------------
__global__ __launch_bounds__(64) void sgemm_n32(
    size_t aOff, int lda, size_t ahs,
    const float* __restrict__ Wext, size_t wOff, int ldb, size_t whs,
    size_t cOff, int ldc, size_t chs, int M, int K) {
    const float* A = g_buf + aOff + (size_t)blockIdx.z * ahs;
    const float* W = (Wext ? Wext : g_buf) + wOff + (size_t)blockIdx.z * whs;
    float* C = g_buf + cOff + (size_t)blockIdx.z * chs;

    __shared__ float As[16][128];
    __shared__ float Bs[16][32];

    const int tid = threadIdx.x;
    const int tx = tid & 3;
    const int ty = tid >> 2;
    const int rowBase = blockIdx.y * 128;

    float acc[8][8];
#pragma unroll
    for (int i = 0; i < 8; i++)
#pragma unroll
        for (int j = 0; j < 8; j++) acc[i][j] = 0.f;

    for (int k0 = 0; k0 < K; k0 += 16) {
#pragma unroll
        for (int i = 0; i < 8; i++) {
            int idx = tid + i * 64;
            int r  = idx >> 2;
            int kc = (idx & 3) << 2;
            int gr = rowBase + r;
            float4 v = make_float4(0.f, 0.f, 0.f, 0.f);
            if (gr < M) v = *reinterpret_cast<const float4*>(A + (size_t)gr * lda + k0 + kc);
            As[kc + 0][r] = v.x; As[kc + 1][r] = v.y;
            As[kc + 2][r] = v.z; As[kc + 3][r] = v.w;
        }
#pragma unroll
        for (int i = 0; i < 2; i++) {
            int idx = tid + i * 64;
            int kk = idx >> 3;
            int cc = (idx & 7) << 2;
            float4 v = *reinterpret_cast<const float4*>(W + (size_t)(k0 + kk) * ldb + cc);
            *reinterpret_cast<float4*>(&Bs[kk][cc]) = v;
        }
        __syncthreads();
#pragma unroll
        for (int kk = 0; kk < 16; kk++) {
            float a[8], b[8];
            *reinterpret_cast<float4*>(&a[0]) = *reinterpret_cast<float4*>(&As[kk][ty * 8]);
            *reinterpret_cast<float4*>(&a[4]) = *reinterpret_cast<float4*>(&As[kk][ty * 8 + 4]);
            *reinterpret_cast<float4*>(&b[0]) = *reinterpret_cast<float4*>(&Bs[kk][tx * 4]);
            *reinterpret_cast<float4*>(&b[4]) = *reinterpret_cast<float4*>(&Bs[kk][16 + tx * 4]);
#pragma unroll
            for (int i = 0; i < 8; i++)
#pragma unroll
                for (int j = 0; j < 8; j++) acc[i][j] += a[i] * b[j];
        }
        __syncthreads();
    }
#pragma unroll
    for (int i = 0; i < 8; i++) {
        int gr = rowBase + ty * 8 + i;
        if (gr >= M) continue;
        float4 v0 = make_float4(acc[i][0], acc[i][1], acc[i][2], acc[i][3]);
        float4 v1 = make_float4(acc[i][4], acc[i][5], acc[i][6], acc[i][7]);
        *reinterpret_cast<float4*>(C + (size_t)gr * ldc + tx * 4) = v0;
        *reinterpret_cast<float4*>(C + (size_t)gr * ldc + 16 + tx * 4) = v1;
    }
}

// ---------------- layer 1 attention: online softmax + v-agg + EA-agg ----------------
// one warp per dst node; lane owns channel c=i*32+lane (per head i) and EA slots f=lane*4..+3
__global__ __launch_bounds__(128) void k_att1() {
    int gt   = blockIdx.x * blockDim.x + threadIdx.x;
    int warp = gt >> 5;
    int lane = gt & 31;
    if (warp >= NN) return;
    int d = warp;

    float q[8];
    float4 P[8];
#pragma unroll
    for (int i = 0; i < 8; i++) {
        q[i] = g_buf[OFF_L1 + (size_t)d * 1024 + i * 32 + lane];
        P[i] = *reinterpret_cast<const float4*>(g_buf + OFF_P1 + (size_t)d * 1024 + i * 128 + lane * 4);
    }
    float m[8], s[8], acc[8];
    float4 ag[8];
#pragma unroll
    for (int i = 0; i < 8; i++) {
        m[i] = -INFINITY; s[i] = 0.f; acc[i] = 0.f;
        ag[i] = make_float4(0.f, 0.f, 0.f, 0.f);
    }

    int beg = g_off[d], end = g_off[d + 1];
    for (int j = beg; j < end; j++) {
        int src = g_src[j];
        const float* K1 = g_buf + OFF_L1 + (size_t)src * 1024 + 256;
        const float* V1 = g_buf + OFF_L1 + (size_t)src * 1024 + 512;
        float4 ea = *reinterpret_cast<const float4*>(g_buf + OFF_EA + (size_t)j * 128 + lane * 4);
        float kv[8], vv[8], p[8];
#pragma unroll
        for (int i = 0; i < 8; i++) {
            kv[i] = K1[i * 32 + lane];
            vv[i] = V1[i * 32 + lane];
            p[i]  = q[i] * kv[i] + ea.x * P[i].x + ea.y * P[i].y + ea.z * P[i].z + ea.w * P[i].w;
        }
#pragma unroll
        for (int o = 16; o >= 1; o >>= 1) {
#pragma unroll
            for (int i = 0; i < 8; i++) p[i] += __shfl_xor_sync(0xffffffffu, p[i], o);
        }
#pragma unroll
        for (int i = 0; i < 8; i++) {
            float a  = p[i] * 0.17677669529663687f;   // 1/sqrt(32)
            float mn = fmaxf(m[i], a);
            float sc = __expf(m[i] - mn);
            float w  = __expf(a - mn);
            s[i]   = s[i] * sc + w;
            acc[i] = acc[i] * sc + w * vv[i];
            ag[i].x = ag[i].x * sc + w * ea.x;
            ag[i].y = ag[i].y * sc + w * ea.y;
            ag[i].z = ag[i].z * sc + w * ea.z;
            ag[i].w = ag[i].w * sc + w * ea.w;
            m[i]   = mn;
        }
    }
#pragma unroll
    for (int i = 0; i < 8; i++) {
        g_buf[OFF_ACC1 + (size_t)d * 256 + i * 32 + lane] = acc[i];
        *reinterpret_cast<float4*>(g_buf + OFF_AGG1 + (size_t)d * 1024 + i * 128 + lane * 4) = ag[i];
        if (lane == i) g_buf[OFF_S1V + (size_t)d * 8 + i] = s[i];
    }
}

// H = relu((ACC1 + AGGP1)/s + S1)
__global__ void k_fin1() {
    int idx = blockIdx.x * blockDim.x + threadIdx.x;
    if (idx >= NN * 256) return;
    int d = idx >> 8, c = idx & 255;
    float s = g_buf[OFF_S1V + (size_t)d * 8 + (c >> 5)] + 1e-16f;
    float o = (g_buf[OFF_ACC1 + idx] + g_buf[OFF_AGGP1 + idx]) / s
            + g_buf[OFF_L1 + (size_t)d * 1024 + 768 + c];
    g_buf[OFF_H + idx] = fmaxf(o, 0.f);
}

// ---------------- layer 2 attention ----------------
__global__ void k_att2() {
    int gt   = blockIdx.x * blockDim.x + threadIdx.x;
    int warp = gt >> 5;
    int lane = gt & 31;
    if (warp >= NN) return;
    int d = warp;

    float q = g_buf[OFF_L2 + (size_t)d * 128 + lane];
    float4 P = *reinterpret_cast<const float4*>(g_buf + OFF_P2 + (size_t)d * 128 + lane * 4);
    float m = -INFINITY, s = 0.f, acc = 0.f;
    float4 ag = make_float4(0.f, 0.f, 0.f, 0.f);

    int beg = g_off[d], end = g_off[d + 1];
    for (int j = beg; j < end; j++) {
        int src = g_src[j];
        float k = g_buf[OFF_L2 + (size_t)src * 128 + 32 + lane];
        float v = g_buf[OFF_L2 + (size_t)src * 128 + 64 + lane];
        float4 ea = *reinterpret_cast<const float4*>(g_buf + OFF_EA + (size_t)j * 128 + lane * 4);
        float p = q * k + ea.x * P.x + ea.y * P.y + ea.z * P.z + ea.w * P.w;
#pragma unroll
        for (int o = 16; o >= 1; o >>= 1) p += __shfl_xor_sync(0xffffffffu, p, o);
        float a  = p * 0.17677669529663687f;
        float mn = fmaxf(m, a);
        float sc = __expf(m - mn);
        float w  = __expf(a - mn);
        s   = s * sc + w;
        acc = acc * sc + w * v;
        ag.x = ag.x * sc + w * ea.x;
        ag.y = ag.y * sc + w * ea.y;
        ag.z = ag.z * sc + w * ea.z;
        ag.w = ag.w * sc + w * ea.w;
        m   = mn;
    }
    g_buf[OFF_ACC2 + (size_t)d * 32 + lane] = acc;
    *reinterpret_cast<float4*>(g_buf + OFF_AGG2 + (size_t)d * 128 + lane * 4) = ag;
    if (lane == 0) g_buf[OFF_S2V + d] = s;
}

// out = relu((ACC2 + AGGP2)/s + S2)
__global__ void k_fin2(float* __restrict__ out) {
    int idx = blockIdx.x * blockDim.x + threadIdx.x;
    if (idx >= NN * 32) return;
    int d = idx >> 5, c = idx & 31;
    float s = g_buf[OFF_S2V + d] + 1e-16f;
    float o = (g_buf[OFF_ACC2 + idx] + g_buf[OFF_AGGP2 + idx]) / s
            + g_buf[OFF_L2 + (size_t)d * 128 + 96 + c];
    out[idx] = fmaxf(o, 0.f);
}

// ---------------- host ----------------
extern "C" void kernel_launch(void* const* d_in, const int* in_sizes, int n_in,
                              void* d_out, int out_size) {
    const float* x   = (const float*)d_in[0];
    const float* lu  = (const float*)d_in[1];
    const int*   ei  = (const int*)d_in[2];     // int32 (JAX x64 disabled)
    const float* t   = (const float*)d_in[3];
    const float* msg = (const float*)d_in[4];
    const float* tw  = (const float*)d_in[5];
    const float* tb  = (const float*)d_in[6];
    const float* Wq1 = (const float*)d_in[7];  const float* bq1 = (const float*)d_in[8];
    const float* Wk1 = (const float*)d_in[9];  const float* bk1 = (const float*)d_in[10];
    const float* Wv1 = (const float*)d_in[11]; const float* bv1 = (const float*)d_in[12];
    const float* We1 = (const float*)d_in[13];
    const float* Ws1 = (const float*)d_in[14]; const float* bs1 = (const float*)d_in[15];
    const float* Wq2 = (const float*)d_in[16]; const float* bq2 = (const float*)d_in[17];
    const float* Wk2 = (const float*)d_in[18]; const float* bk2 = (const float*)d_in[19];
    const float* Wv2 = (const float*)d_in[20]; const float* bv2 = (const float*)d_in[21];
    const float* We2 = (const float*)d_in[22];
    const float* Ws2 = (const float*)d_in[23]; const float* bs2 = (const float*)d_in[24];
    float* out = (float*)d_out;

    const int MB = (NN + 127) / 128;   // 391 row blocks

    // CSR build
    k_zero<<<(NN + 255) / 256, 256>>>();
    k_hist<<<(EE + 255) / 256, 256>>>(ei);
    k_scan<<<1, 1024>>>();
    k_scatter<<<(EE + 255) / 256, 256>>>(ei);

    // weight prep
    k_cat1<<<(128 * 1024 + 1024 + 255) / 256, 256>>>(Wq1, Wk1, Wv1, Ws1, bq1, bk1, bv1, bs1);
    k_cat2<<<(256 * 128 + 128 + 255) / 256, 256>>>(Wq2, Wk2, Wv2, Ws2, bq2, bk2, bv2, bs2);
    k_wt<<<(128 * 256 + 128 * 32 + 255) / 256, 256>>>(We1, We2);

    // sorted edge attributes
    {
        long long tot = (long long)EE * EDIM;
        k_ea<<<(unsigned)((tot + 255) / 256), 256>>>(lu, t, msg, tw, tb);
    }

    // L1 = x @ WC1 + BC1    [NN,128]@[128,1024]
    sgemm_128<<<dim3(8, MB, 1), 256>>>(x, 0, IN_CH, 0,
                                       nullptr, OFF_WC1, 1024, 0,
                                       1, OFF_BC1,
                                       OFF_L1, 1024, 0, NN, IN_CH, 1024);
    // P1_h = Q1_h @ We1_h^T  8x [NN,32]@[32,128]
    sgemm_128<<<dim3(1, MB, 8), 256>>>(nullptr, OFF_L1, 1024, 32,
                                       nullptr, OFF_WT1, 128, 32 * 128,
                                       0, 0,
                                       OFF_P1, 1024, 128, NN, 32, 128);
    // layer-1 attention
    k_att1<<<(NN * 32 + 127) / 128, 128>>>();
    // AGGP1_h = AGG1_h @ We1_h  8x [NN,128]@[128,32]
    sgemm_n32<<<dim3(1, MB, 8), 64>>>(OFF_AGG1, 1024, 128,
                                      We1, 0, HID, 32,
                                      OFF_AGGP1, 256, 32, NN, 128);
    k_fin1<<<(NN * 256 + 255) / 256, 256>>>();

    // L2 = H @ WC2 + BC2    [NN,256]@[256,128]
    sgemm_128<<<dim3(1, MB, 1), 256>>>(nullptr, OFF_H, HID, 0,
                                       nullptr, OFF_WC2, 128, 0,
                                       1, OFF_BC2,
                                       OFF_L2, 128, 0, NN, HID, 128);
    // P2 = Q2 @ We2^T  [NN,32]@[32,128]
    sgemm_128<<<dim3(1, MB, 1), 256>>>(nullptr, OFF_L2, 128, 0,
                                       nullptr, OFF_WT2, 128, 0,
                                       0, 0,
                                       OFF_P2, 128, 0, NN, 32, 128);
    // layer-2 attention
    k_att2<<<(NN * 32 + 255) / 256, 256>>>();
    // AGGP2 = AGG2 @ We2  [NN,128]@[128,32]
    sgemm_n32<<<dim3(1, MB, 1), 64>>>(OFF_AGG2, 128, 0,
                                      We2, 0, CH, 0,
                                      OFF_AGGP2, 32, 0, NN, 128);
    k_fin2<<<(NN * 32 + 255) / 256, 256>>>(out);
}